// round 11
// baseline (speedup 1.0000x reference)
#include <cuda_runtime.h>
#include <cstddef>
#include <cstdint>

// Problem constants
constexpr int B_ = 4, C_ = 16, S_ = 512, E_ = 512, H_ = 8, HD_ = 64;
constexpr int TOKENS_ = B_ * C_ * S_;                     // 32768
constexpr size_t OUT_ELEMS  = (size_t)TOKENS_ * E_;       // 16,777,216
constexpr size_t ATTN_ELEMS = (size_t)B_ * H_ * C_ * S_ * S_; // 134,217,728

// ---------------------------------------------------------------------------
// Scratch: __device__ globals (allocation APIs are banned; this is the
// sanctioned workaround). q/k/v/ctx = 4 x 64MB. attn fallback 512MB only used
// if the harness does not expose the attn_weights output region in d_out.
// ---------------------------------------------------------------------------
__device__ __align__(128) float g_q[OUT_ELEMS];
__device__ __align__(128) float g_k[OUT_ELEMS];
__device__ __align__(128) float g_v[OUT_ELEMS];
__device__ __align__(128) float g_ctx[OUT_ELEMS];
__device__ __align__(128) float g_attn_fb[ATTN_ELEMS];

// ---------------------------------------------------------------------------
// SGEMM (TN): C[M,N] = alpha * A[M,K] @ B[N,K]^T (+ bias[N])
// Both operands row-major with K contiguous. BM=BN=128, BK=8, 256 threads,
// 8x8 microtile per thread, register-prefetch double buffering.
// MODE 0: plain (projections).  Dims must divide tiles (they do here).
// MODE 1: attention scores. blockIdx.z = (b*H+h)*C + c selects the head slice
//         of g_q/g_k (offset h*HD within E-wide rows) and the attn output
//         block at z*S*S.
// ---------------------------------------------------------------------------
constexpr int BM = 128, BN = 128, BK = 8;

template <int MODE>
__global__ void __launch_bounds__(256, 2)
sgemm_tn(const float* __restrict__ Ag, const float* __restrict__ Bg,
         float* __restrict__ Cg, int lda, int ldb, int ldc, int Ktiles,
         float alpha, const float* __restrict__ bias)
{
    __shared__ float As[BK][BM + 4];   // pitch 132: conflict-free transposed stores
    __shared__ float Bs[BK][BN + 4];

    const float* A = Ag;
    const float* Bm = Bg;
    float* Cp = Cg;
    if (MODE == 1) {
        int z = blockIdx.z;
        int c = z % C_;
        int h = (z / C_) % H_;
        int b = z / (C_ * H_);
        size_t off = ((size_t)(b * C_ + c) * S_) * E_ + (size_t)h * HD_;
        A  = Ag + off;
        Bm = Bg + off;
        Cp = Cg + (size_t)z * S_ * S_;   // attn layout (b,h,c,q,k)
    }

    const int tid = threadIdx.x;
    const int bm = blockIdx.y * BM;
    const int bn = blockIdx.x * BN;

    // Global tile loaders: one float4 along K per thread, per operand.
    const int arow = tid >> 1;         // 0..127
    const int acol = (tid & 1) * 4;    // 0 or 4
    const float* Aptr = A  + (size_t)(bm + arow) * lda + acol;
    const float* Bptr = Bm + (size_t)(bn + arow) * ldb + acol;

    const int ty = tid >> 4;           // 0..15
    const int tx = tid & 15;           // 0..15

    float acc[8][8];
#pragma unroll
    for (int i = 0; i < 8; i++)
#pragma unroll
        for (int j = 0; j < 8; j++) acc[i][j] = 0.0f;

    float4 pa = *(const float4*)Aptr;
    float4 pb = *(const float4*)Bptr;

    for (int kt = 0; kt < Ktiles; kt++) {
        // transposed stores (K-major -> [k][m]); pitch 132 => conflict-free
        As[acol + 0][arow] = pa.x; As[acol + 1][arow] = pa.y;
        As[acol + 2][arow] = pa.z; As[acol + 3][arow] = pa.w;
        Bs[acol + 0][arow] = pb.x; Bs[acol + 1][arow] = pb.y;
        Bs[acol + 2][arow] = pb.z; Bs[acol + 3][arow] = pb.w;
        __syncthreads();

        if (kt + 1 < Ktiles) {          // prefetch next K-slab into registers
            pa = *(const float4*)(Aptr + (size_t)(kt + 1) * BK);
            pb = *(const float4*)(Bptr + (size_t)(kt + 1) * BK);
        }

#pragma unroll
        for (int kk = 0; kk < BK; kk++) {
            float4 a0 = *(const float4*)&As[kk][ty * 8];
            float4 a1 = *(const float4*)&As[kk][ty * 8 + 4];
            float4 b0 = *(const float4*)&Bs[kk][tx * 8];
            float4 b1 = *(const float4*)&Bs[kk][tx * 8 + 4];
            float ar[8] = {a0.x, a0.y, a0.z, a0.w, a1.x, a1.y, a1.z, a1.w};
            float br[8] = {b0.x, b0.y, b0.z, b0.w, b1.x, b1.y, b1.z, b1.w};
#pragma unroll
            for (int i = 0; i < 8; i++)
#pragma unroll
                for (int j = 0; j < 8; j++)
                    acc[i][j] += ar[i] * br[j];
        }
        __syncthreads();
    }

    // Epilogue
    float bv0[4] = {0, 0, 0, 0}, bv1[4] = {0, 0, 0, 0};
    if (bias) {
        float4 t0 = *(const float4*)&bias[bn + tx * 8];
        float4 t1 = *(const float4*)&bias[bn + tx * 8 + 4];
        bv0[0] = t0.x; bv0[1] = t0.y; bv0[2] = t0.z; bv0[3] = t0.w;
        bv1[0] = t1.x; bv1[1] = t1.y; bv1[2] = t1.z; bv1[3] = t1.w;
    }
#pragma unroll
    for (int i = 0; i < 8; i++) {
        int row = bm + ty * 8 + i;
        float* crow = Cp + (size_t)row * ldc + bn + tx * 8;
        float4 v0, v1;
        v0.x = acc[i][0] * alpha + bv0[0];
        v0.y = acc[i][1] * alpha + bv0[1];
        v0.z = acc[i][2] * alpha + bv0[2];
        v0.w = acc[i][3] * alpha + bv0[3];
        v1.x = acc[i][4] * alpha + bv1[0];
        v1.y = acc[i][5] * alpha + bv1[1];
        v1.z = acc[i][6] * alpha + bv1[2];
        v1.w = acc[i][7] * alpha + bv1[3];
        *(float4*)crow       = v0;
        *(float4*)(crow + 4) = v1;
    }
}

// ---------------------------------------------------------------------------
// Context GEMM (NN): per batch z=(b*H+h)*C+c:
//   ctx[q, d] = sum_k attn[z][q][k] * V[(b,c,k)][h*64 + d]
// BM=128 (q), BN=64 (d), BK=16. 256 threads, 8x4 microtile.
// Writes into g_ctx at (b,c,s, h*64+d) so the output projection consumes a
// plain (TOKENS x E) matrix (heads already merged).
// ---------------------------------------------------------------------------
constexpr int XBM = 128, XBN = 64, XBK = 16;

__global__ void __launch_bounds__(256, 2)
ctx_gemm(const float* __restrict__ attn, const float* __restrict__ Vg,
         float* __restrict__ Cg)
{
    __shared__ float As[XBK][XBM + 4];   // attn tile, transposed [k][q]
    __shared__ float Bs[XBK][XBN + 4];   // V tile, natural [k][d]

    const int z = blockIdx.z;
    const int c = z % C_;
    const int h = (z / C_) % H_;
    const int b = z / (C_ * H_);

    const float* A  = attn + (size_t)z * S_ * S_;                       // lda=S_
    const float* Bv = Vg + ((size_t)(b * C_ + c) * S_) * E_ + (size_t)h * HD_; // ldb=E_
    float*       Cp = Cg + ((size_t)(b * C_ + c) * S_) * E_ + (size_t)h * HD_; // ldc=E_

    const int tid = threadIdx.x;
    const int bm = blockIdx.y * XBM;

    // A: 128 rows x 16 k = 512 float4 -> 2 per thread
    const int arow = tid >> 1;
    const int acol = (tid & 1) * 8;
    const float* Aptr = A + (size_t)(bm + arow) * S_ + acol;

    // B: 16 rows x 64 = 256 float4 -> 1 per thread
    const int brow = tid >> 4;          // 0..15
    const int bcol = (tid & 15) * 4;
    const float* Bptr = Bv + (size_t)brow * E_ + bcol;

    const int ty = tid >> 4;            // rows: ty*8
    const int tx = tid & 15;            // cols: tx*4

    float acc[8][4];
#pragma unroll
    for (int i = 0; i < 8; i++)
#pragma unroll
        for (int j = 0; j < 4; j++) acc[i][j] = 0.0f;

    float4 pa0 = *(const float4*)Aptr;
    float4 pa1 = *(const float4*)(Aptr + 4);
    float4 pb  = *(const float4*)Bptr;

    const int Ktiles = S_ / XBK;        // 32
    for (int kt = 0; kt < Ktiles; kt++) {
        As[acol + 0][arow] = pa0.x; As[acol + 1][arow] = pa0.y;
        As[acol + 2][arow] = pa0.z; As[acol + 3][arow] = pa0.w;
        As[acol + 4][arow] = pa1.x; As[acol + 5][arow] = pa1.y;
        As[acol + 6][arow] = pa1.z; As[acol + 7][arow] = pa1.w;
        *(float4*)&Bs[brow][bcol] = pb;
        __syncthreads();

        if (kt + 1 < Ktiles) {
            pa0 = *(const float4*)(Aptr + (size_t)(kt + 1) * XBK);
            pa1 = *(const float4*)(Aptr + (size_t)(kt + 1) * XBK + 4);
            pb  = *(const float4*)(Bptr + (size_t)(kt + 1) * XBK * E_);
        }

#pragma unroll
        for (int kk = 0; kk < XBK; kk++) {
            float4 a0 = *(const float4*)&As[kk][ty * 8];
            float4 a1 = *(const float4*)&As[kk][ty * 8 + 4];
            float4 b0 = *(const float4*)&Bs[kk][tx * 4];
            float ar[8] = {a0.x, a0.y, a0.z, a0.w, a1.x, a1.y, a1.z, a1.w};
            float br[4] = {b0.x, b0.y, b0.z, b0.w};
#pragma unroll
            for (int i = 0; i < 8; i++)
#pragma unroll
                for (int j = 0; j < 4; j++)
                    acc[i][j] += ar[i] * br[j];
        }
        __syncthreads();
    }

#pragma unroll
    for (int i = 0; i < 8; i++) {
        int row = bm + ty * 8 + i;
        float4 v;
        v.x = acc[i][0]; v.y = acc[i][1]; v.z = acc[i][2]; v.w = acc[i][3];
        *(float4*)(Cp + (size_t)row * E_ + tx * 4) = v;
    }
}

// ---------------------------------------------------------------------------
// Row softmax, in place, rows of exactly 512 floats. One warp per row:
// 4 x float4 per lane, warp shfl reductions for max and sum.
// ---------------------------------------------------------------------------
__global__ void softmax_rows(float* __restrict__ attn)
{
    const int warp = (blockIdx.x * blockDim.x + threadIdx.x) >> 5;
    const int lane = threadIdx.x & 31;
    float* row = attn + (size_t)warp * S_;

    float4 v[4];
    float mx = -3.0e38f;
#pragma unroll
    for (int i = 0; i < 4; i++) {
        v[i] = *(const float4*)(row + (size_t)(lane + 32 * i) * 4);
        mx = fmaxf(mx, fmaxf(fmaxf(v[i].x, v[i].y), fmaxf(v[i].z, v[i].w)));
    }
#pragma unroll
    for (int s = 16; s > 0; s >>= 1)
        mx = fmaxf(mx, __shfl_xor_sync(0xffffffffu, mx, s));

    float sum = 0.0f;
#pragma unroll
    for (int i = 0; i < 4; i++) {
        v[i].x = __expf(v[i].x - mx);
        v[i].y = __expf(v[i].y - mx);
        v[i].z = __expf(v[i].z - mx);
        v[i].w = __expf(v[i].w - mx);
        sum += v[i].x + v[i].y + v[i].z + v[i].w;
    }
#pragma unroll
    for (int s = 16; s > 0; s >>= 1)
        sum += __shfl_xor_sync(0xffffffffu, sum, s);

    const float inv = 1.0f / sum;
#pragma unroll
    for (int i = 0; i < 4; i++) {
        v[i].x *= inv; v[i].y *= inv; v[i].z *= inv; v[i].w *= inv;
        *(float4*)(row + (size_t)(lane + 32 * i) * 4) = v[i];
    }
}

// ---------------------------------------------------------------------------
// Launch: 7 kernels on the default stream (graph-capturable; no sync, no alloc)
// ---------------------------------------------------------------------------
extern "C" void kernel_launch(void* const* d_in, const int* in_sizes, int n_in,
                              void* d_out, int out_size)
{
    const float* q  = (const float*)d_in[0];
    const float* k  = (const float*)d_in[1];
    const float* v  = (const float*)d_in[2];
    const float* Wq = (const float*)d_in[3];
    const float* bq = (const float*)d_in[4];
    const float* Wk = (const float*)d_in[5];
    const float* bk = (const float*)d_in[6];
    const float* Wv = (const float*)d_in[7];
    const float* bv = (const float*)d_in[8];
    const float* Wo = (const float*)d_in[9];
    const float* bo = (const float*)d_in[10];
    float* out = (float*)d_out;

    float *gq, *gk, *gv, *gctx, *gfb;
    cudaGetSymbolAddress((void**)&gq,   g_q);
    cudaGetSymbolAddress((void**)&gk,   g_k);
    cudaGetSymbolAddress((void**)&gv,   g_v);
    cudaGetSymbolAddress((void**)&gctx, g_ctx);
    cudaGetSymbolAddress((void**)&gfb,  g_attn_fb);

    // attn_weights is the second reference output; if d_out carries both
    // outputs concatenated, write the weights there, else to scratch.
    float* attn = ((size_t)out_size >= OUT_ELEMS + ATTN_ELEMS)
                      ? (out + OUT_ELEMS)
                      : gfb;

    dim3 blk(256);

    // 1-3) Q/K/V projections: (32768 x 512) = X @ W^T + b
    dim3 gproj(E_ / BN, TOKENS_ / BM, 1);
    sgemm_tn<0><<<gproj, blk>>>(q, Wq, gq, E_, E_, E_, E_ / BK, 1.0f, bq);
    sgemm_tn<0><<<gproj, blk>>>(k, Wk, gk, E_, E_, E_, E_ / BK, 1.0f, bk);
    sgemm_tn<0><<<gproj, blk>>>(v, Wv, gv, E_, E_, E_, E_ / BK, 1.0f, bv);

    // 4) scores = (Q @ K^T) * 1/sqrt(64), per (b,h,c) batch
    dim3 gsc(S_ / BN, S_ / BM, B_ * H_ * C_);
    sgemm_tn<1><<<gsc, blk>>>(gq, gk, attn, E_, E_, S_, HD_ / BK, 0.125f,
                              nullptr);

    // 5) softmax over last dim (rows of 512), in place
    const int nrows = B_ * H_ * C_ * S_;      // 262144
    softmax_rows<<<nrows / 8, 256>>>(attn);

    // 6) context = attn @ V, heads merged into (b,c,s,E) layout
    dim3 gcx(1, S_ / XBM, B_ * H_ * C_);
    ctx_gemm<<<gcx, blk>>>(attn, gv, gctx);

    // 7) output projection: out = ctx @ Wo^T + bo
    sgemm_tn<0><<<gproj, blk>>>(gctx, Wo, out, E_, E_, E_, E_ / BK, 1.0f, bo);
}

// round 12
// speedup vs baseline: 1.0005x; 1.0005x over previous
#include <cuda_runtime.h>
#include <cstddef>
#include <cstdint>

// Problem constants
constexpr int B_ = 4, C_ = 16, S_ = 512, E_ = 512, H_ = 8, HD_ = 64;
constexpr int TOKENS_ = B_ * C_ * S_;                     // 32768
constexpr size_t OUT_ELEMS  = (size_t)TOKENS_ * E_;       // 16,777,216
constexpr size_t ATTN_ELEMS = (size_t)B_ * H_ * C_ * S_ * S_; // 134,217,728

// ---------------------------------------------------------------------------
// Scratch: __device__ globals (allocation APIs are banned; this is the
// sanctioned workaround). q/k/v/ctx = 4 x 64MB. attn fallback 512MB only used
// if the harness does not expose the attn_weights output region in d_out.
// ---------------------------------------------------------------------------
__device__ __align__(128) float g_q[OUT_ELEMS];
__device__ __align__(128) float g_k[OUT_ELEMS];
__device__ __align__(128) float g_v[OUT_ELEMS];
__device__ __align__(128) float g_ctx[OUT_ELEMS];
__device__ __align__(128) float g_attn_fb[ATTN_ELEMS];

// ---------------------------------------------------------------------------
// SGEMM (TN): C[M,N] = alpha * A[M,K] @ B[N,K]^T (+ bias[N])
// Both operands row-major with K contiguous. BM=BN=128, BK=8, 256 threads,
// 8x8 microtile per thread, register-prefetch double buffering.
// MODE 0: plain (projections).  Dims must divide tiles (they do here).
// MODE 1: attention scores. blockIdx.z = (b*H+h)*C + c selects the head slice
//         of g_q/g_k (offset h*HD within E-wide rows) and the attn output
//         block at z*S*S.
// ---------------------------------------------------------------------------
constexpr int BM = 128, BN = 128, BK = 8;

template <int MODE>
__global__ void __launch_bounds__(256, 2)
sgemm_tn(const float* __restrict__ Ag, const float* __restrict__ Bg,
         float* __restrict__ Cg, int lda, int ldb, int ldc, int Ktiles,
         float alpha, const float* __restrict__ bias)
{
    __shared__ float As[BK][BM + 4];   // pitch 132: conflict-free transposed stores
    __shared__ float Bs[BK][BN + 4];

    const float* A = Ag;
    const float* Bm = Bg;
    float* Cp = Cg;
    if (MODE == 1) {
        int z = blockIdx.z;
        int c = z % C_;
        int h = (z / C_) % H_;
        int b = z / (C_ * H_);
        size_t off = ((size_t)(b * C_ + c) * S_) * E_ + (size_t)h * HD_;
        A  = Ag + off;
        Bm = Bg + off;
        Cp = Cg + (size_t)z * S_ * S_;   // attn layout (b,h,c,q,k)
    }

    const int tid = threadIdx.x;
    const int bm = blockIdx.y * BM;
    const int bn = blockIdx.x * BN;

    // Global tile loaders: one float4 along K per thread, per operand.
    const int arow = tid >> 1;         // 0..127
    const int acol = (tid & 1) * 4;    // 0 or 4
    const float* Aptr = A  + (size_t)(bm + arow) * lda + acol;
    const float* Bptr = Bm + (size_t)(bn + arow) * ldb + acol;

    const int ty = tid >> 4;           // 0..15
    const int tx = tid & 15;           // 0..15

    float acc[8][8];
#pragma unroll
    for (int i = 0; i < 8; i++)
#pragma unroll
        for (int j = 0; j < 8; j++) acc[i][j] = 0.0f;

    float4 pa = *(const float4*)Aptr;
    float4 pb = *(const float4*)Bptr;

    for (int kt = 0; kt < Ktiles; kt++) {
        // transposed stores (K-major -> [k][m]); pitch 132 => conflict-free
        As[acol + 0][arow] = pa.x; As[acol + 1][arow] = pa.y;
        As[acol + 2][arow] = pa.z; As[acol + 3][arow] = pa.w;
        Bs[acol + 0][arow] = pb.x; Bs[acol + 1][arow] = pb.y;
        Bs[acol + 2][arow] = pb.z; Bs[acol + 3][arow] = pb.w;
        __syncthreads();

        if (kt + 1 < Ktiles) {          // prefetch next K-slab into registers
            pa = *(const float4*)(Aptr + (size_t)(kt + 1) * BK);
            pb = *(const float4*)(Bptr + (size_t)(kt + 1) * BK);
        }

#pragma unroll
        for (int kk = 0; kk < BK; kk++) {
            float4 a0 = *(const float4*)&As[kk][ty * 8];
            float4 a1 = *(const float4*)&As[kk][ty * 8 + 4];
            float4 b0 = *(const float4*)&Bs[kk][tx * 8];
            float4 b1 = *(const float4*)&Bs[kk][tx * 8 + 4];
            float ar[8] = {a0.x, a0.y, a0.z, a0.w, a1.x, a1.y, a1.z, a1.w};
            float br[8] = {b0.x, b0.y, b0.z, b0.w, b1.x, b1.y, b1.z, b1.w};
#pragma unroll
            for (int i = 0; i < 8; i++)
#pragma unroll
                for (int j = 0; j < 8; j++)
                    acc[i][j] += ar[i] * br[j];
        }
        __syncthreads();
    }

    // Epilogue
    float bv0[4] = {0, 0, 0, 0}, bv1[4] = {0, 0, 0, 0};
    if (bias) {
        float4 t0 = *(const float4*)&bias[bn + tx * 8];
        float4 t1 = *(const float4*)&bias[bn + tx * 8 + 4];
        bv0[0] = t0.x; bv0[1] = t0.y; bv0[2] = t0.z; bv0[3] = t0.w;
        bv1[0] = t1.x; bv1[1] = t1.y; bv1[2] = t1.z; bv1[3] = t1.w;
    }
#pragma unroll
    for (int i = 0; i < 8; i++) {
        int row = bm + ty * 8 + i;
        float* crow = Cp + (size_t)row * ldc + bn + tx * 8;
        float4 v0, v1;
        v0.x = acc[i][0] * alpha + bv0[0];
        v0.y = acc[i][1] * alpha + bv0[1];
        v0.z = acc[i][2] * alpha + bv0[2];
        v0.w = acc[i][3] * alpha + bv0[3];
        v1.x = acc[i][4] * alpha + bv1[0];
        v1.y = acc[i][5] * alpha + bv1[1];
        v1.z = acc[i][6] * alpha + bv1[2];
        v1.w = acc[i][7] * alpha + bv1[3];
        *(float4*)crow       = v0;
        *(float4*)(crow + 4) = v1;
    }
}

// ---------------------------------------------------------------------------
// Context GEMM (NN): per batch z=(b*H+h)*C+c:
//   ctx[q, d] = sum_k attn[z][q][k] * V[(b,c,k)][h*64 + d]
// BM=128 (q), BN=64 (d), BK=16. 256 threads, 8x4 microtile.
// Writes into g_ctx at (b,c,s, h*64+d) so the output projection consumes a
// plain (TOKENS x E) matrix (heads already merged).
// ---------------------------------------------------------------------------
constexpr int XBM = 128, XBN = 64, XBK = 16;

__global__ void __launch_bounds__(256, 2)
ctx_gemm(const float* __restrict__ attn, const float* __restrict__ Vg,
         float* __restrict__ Cg)
{
    __shared__ float As[XBK][XBM + 4];   // attn tile, transposed [k][q]
    __shared__ float Bs[XBK][XBN + 4];   // V tile, natural [k][d]

    const int z = blockIdx.z;
    const int c = z % C_;
    const int h = (z / C_) % H_;
    const int b = z / (C_ * H_);

    const float* A  = attn + (size_t)z * S_ * S_;                       // lda=S_
    const float* Bv = Vg + ((size_t)(b * C_ + c) * S_) * E_ + (size_t)h * HD_; // ldb=E_
    float*       Cp = Cg + ((size_t)(b * C_ + c) * S_) * E_ + (size_t)h * HD_; // ldc=E_

    const int tid = threadIdx.x;
    const int bm = blockIdx.y * XBM;

    // A: 128 rows x 16 k = 512 float4 -> 2 per thread
    const int arow = tid >> 1;
    const int acol = (tid & 1) * 8;
    const float* Aptr = A + (size_t)(bm + arow) * S_ + acol;

    // B: 16 rows x 64 = 256 float4 -> 1 per thread
    const int brow = tid >> 4;          // 0..15
    const int bcol = (tid & 15) * 4;
    const float* Bptr = Bv + (size_t)brow * E_ + bcol;

    const int ty = tid >> 4;            // rows: ty*8
    const int tx = tid & 15;            // cols: tx*4

    float acc[8][4];
#pragma unroll
    for (int i = 0; i < 8; i++)
#pragma unroll
        for (int j = 0; j < 4; j++) acc[i][j] = 0.0f;

    float4 pa0 = *(const float4*)Aptr;
    float4 pa1 = *(const float4*)(Aptr + 4);
    float4 pb  = *(const float4*)Bptr;

    const int Ktiles = S_ / XBK;        // 32
    for (int kt = 0; kt < Ktiles; kt++) {
        As[acol + 0][arow] = pa0.x; As[acol + 1][arow] = pa0.y;
        As[acol + 2][arow] = pa0.z; As[acol + 3][arow] = pa0.w;
        As[acol + 4][arow] = pa1.x; As[acol + 5][arow] = pa1.y;
        As[acol + 6][arow] = pa1.z; As[acol + 7][arow] = pa1.w;
        *(float4*)&Bs[brow][bcol] = pb;
        __syncthreads();

        if (kt + 1 < Ktiles) {
            pa0 = *(const float4*)(Aptr + (size_t)(kt + 1) * XBK);
            pa1 = *(const float4*)(Aptr + (size_t)(kt + 1) * XBK + 4);
            pb  = *(const float4*)(Bptr + (size_t)(kt + 1) * XBK * E_);
        }

#pragma unroll
        for (int kk = 0; kk < XBK; kk++) {
            float4 a0 = *(const float4*)&As[kk][ty * 8];
            float4 a1 = *(const float4*)&As[kk][ty * 8 + 4];
            float4 b0 = *(const float4*)&Bs[kk][tx * 4];
            float ar[8] = {a0.x, a0.y, a0.z, a0.w, a1.x, a1.y, a1.z, a1.w};
            float br[4] = {b0.x, b0.y, b0.z, b0.w};
#pragma unroll
            for (int i = 0; i < 8; i++)
#pragma unroll
                for (int j = 0; j < 4; j++)
                    acc[i][j] += ar[i] * br[j];
        }
        __syncthreads();
    }

#pragma unroll
    for (int i = 0; i < 8; i++) {
        int row = bm + ty * 8 + i;
        float4 v;
        v.x = acc[i][0]; v.y = acc[i][1]; v.z = acc[i][2]; v.w = acc[i][3];
        *(float4*)(Cp + (size_t)row * E_ + tx * 4) = v;
    }
}

// ---------------------------------------------------------------------------
// Row softmax, in place, rows of exactly 512 floats. One warp per row:
// 4 x float4 per lane, warp shfl reductions for max and sum.
// ---------------------------------------------------------------------------
__global__ void softmax_rows(float* __restrict__ attn)
{
    const int warp = (blockIdx.x * blockDim.x + threadIdx.x) >> 5;
    const int lane = threadIdx.x & 31;
    float* row = attn + (size_t)warp * S_;

    float4 v[4];
    float mx = -3.0e38f;
#pragma unroll
    for (int i = 0; i < 4; i++) {
        v[i] = *(const float4*)(row + (size_t)(lane + 32 * i) * 4);
        mx = fmaxf(mx, fmaxf(fmaxf(v[i].x, v[i].y), fmaxf(v[i].z, v[i].w)));
    }
#pragma unroll
    for (int s = 16; s > 0; s >>= 1)
        mx = fmaxf(mx, __shfl_xor_sync(0xffffffffu, mx, s));

    float sum = 0.0f;
#pragma unroll
    for (int i = 0; i < 4; i++) {
        v[i].x = __expf(v[i].x - mx);
        v[i].y = __expf(v[i].y - mx);
        v[i].z = __expf(v[i].z - mx);
        v[i].w = __expf(v[i].w - mx);
        sum += v[i].x + v[i].y + v[i].z + v[i].w;
    }
#pragma unroll
    for (int s = 16; s > 0; s >>= 1)
        sum += __shfl_xor_sync(0xffffffffu, sum, s);

    const float inv = 1.0f / sum;
#pragma unroll
    for (int i = 0; i < 4; i++) {
        v[i].x *= inv; v[i].y *= inv; v[i].z *= inv; v[i].w *= inv;
        *(float4*)(row + (size_t)(lane + 32 * i) * 4) = v[i];
    }
}

// ---------------------------------------------------------------------------
// Launch: 7 kernels on the default stream (graph-capturable; no sync, no alloc)
// ---------------------------------------------------------------------------
extern "C" void kernel_launch(void* const* d_in, const int* in_sizes, int n_in,
                              void* d_out, int out_size)
{
    const float* q  = (const float*)d_in[0];
    const float* k  = (const float*)d_in[1];
    const float* v  = (const float*)d_in[2];
    const float* Wq = (const float*)d_in[3];
    const float* bq = (const float*)d_in[4];
    const float* Wk = (const float*)d_in[5];
    const float* bk = (const float*)d_in[6];
    const float* Wv = (const float*)d_in[7];
    const float* bv = (const float*)d_in[8];
    const float* Wo = (const float*)d_in[9];
    const float* bo = (const float*)d_in[10];
    float* out = (float*)d_out;

    float *gq, *gk, *gv, *gctx, *gfb;
    cudaGetSymbolAddress((void**)&gq,   g_q);
    cudaGetSymbolAddress((void**)&gk,   g_k);
    cudaGetSymbolAddress((void**)&gv,   g_v);
    cudaGetSymbolAddress((void**)&gctx, g_ctx);
    cudaGetSymbolAddress((void**)&gfb,  g_attn_fb);

    // attn_weights is the second reference output; if d_out carries both
    // outputs concatenated, write the weights there, else to scratch.
    float* attn = ((size_t)out_size >= OUT_ELEMS + ATTN_ELEMS)
                      ? (out + OUT_ELEMS)
                      : gfb;

    dim3 blk(256);

    // 1-3) Q/K/V projections: (32768 x 512) = X @ W^T + b
    dim3 gproj(E_ / BN, TOKENS_ / BM, 1);
    sgemm_tn<0><<<gproj, blk>>>(q, Wq, gq, E_, E_, E_, E_ / BK, 1.0f, bq);
    sgemm_tn<0><<<gproj, blk>>>(k, Wk, gk, E_, E_, E_, E_ / BK, 1.0f, bk);
    sgemm_tn<0><<<gproj, blk>>>(v, Wv, gv, E_, E_, E_, E_ / BK, 1.0f, bv);

    // 4) scores = (Q @ K^T) * 1/sqrt(64), per (b,h,c) batch
    dim3 gsc(S_ / BN, S_ / BM, B_ * H_ * C_);
    sgemm_tn<1><<<gsc, blk>>>(gq, gk, attn, E_, E_, S_, HD_ / BK, 0.125f,
                              nullptr);

    // 5) softmax over last dim (rows of 512), in place
    const int nrows = B_ * H_ * C_ * S_;      // 262144
    softmax_rows<<<nrows / 8, 256>>>(attn);

    // 6) context = attn @ V, heads merged into (b,c,s,E) layout
    dim3 gcx(1, S_ / XBM, B_ * H_ * C_);
    ctx_gemm<<<gcx, blk>>>(attn, gv, gctx);

    // 7) output projection: out = ctx @ Wo^T + bo
    sgemm_tn<0><<<gproj, blk>>>(gctx, Wo, out, E_, E_, E_, E_ / BK, 1.0f, bo);
}

// round 14
// speedup vs baseline: 1.4020x; 1.4014x over previous
#include <cuda_runtime.h>
#include <cstddef>
#include <cstdint>

// Problem constants
constexpr int B_ = 4, C_ = 16, S_ = 512, E_ = 512, H_ = 8, HD_ = 64;
constexpr int TOKENS_ = B_ * C_ * S_;                         // 32768
constexpr size_t OUT_ELEMS  = (size_t)TOKENS_ * E_;           // 16,777,216
constexpr size_t ATTN_ELEMS = (size_t)B_ * H_ * C_ * S_ * S_; // 134,217,728

// ---------------------------------------------------------------------------
// Scratch (__device__ globals: allocation APIs are banned)
// ---------------------------------------------------------------------------
__device__ __align__(128) float g_q[OUT_ELEMS];
__device__ __align__(128) float g_k[OUT_ELEMS];
__device__ __align__(128) float g_v[OUT_ELEMS];
__device__ __align__(128) float g_vt[OUT_ELEMS];   // per-(b,c) transposed V proj
__device__ __align__(128) float g_ctx[OUT_ELEMS];
__device__ __align__(128) float g_attn_fb[ATTN_ELEMS];

// ---------------------------------------------------------------------------
// tf32 helpers (baseline PTX, valid for sm_103 family target)
// ---------------------------------------------------------------------------
__device__ __forceinline__ float to_tf32(float x) {
    float r;
    asm("cvt.rna.tf32.f32 %0, %1;" : "=f"(r) : "f"(x));
    return r;
}
__device__ __forceinline__ float4 tf32x4(float4 v) {
    v.x = to_tf32(v.x); v.y = to_tf32(v.y);
    v.z = to_tf32(v.z); v.w = to_tf32(v.w);
    return v;
}
__device__ __forceinline__ void mma_tf32(float* c, const uint32_t* a, const uint32_t* b) {
    asm volatile(
        "mma.sync.aligned.m16n8k8.row.col.f32.tf32.tf32.f32 "
        "{%0,%1,%2,%3}, {%4,%5,%6,%7}, {%8,%9}, {%0,%1,%2,%3};"
        : "+f"(c[0]), "+f"(c[1]), "+f"(c[2]), "+f"(c[3])
        : "r"(a[0]), "r"(a[1]), "r"(a[2]), "r"(a[3]), "r"(b[0]), "r"(b[1]));
}

// ---------------------------------------------------------------------------
// tf32 mma.sync GEMM (TN): C[M,N] = alpha * A[M,K] @ B[N,K]^T (+ bias[N])
// BM=128, BK=16. BN_=128 -> 512 threads (4x4 warps); BN_=64 -> 256 (4x2).
// Warp tile 32x32 = 2x4 m16n8k8 tiles. Register-prefetch double buffering.
// MODE 0: plain. MODE 1: scores (z=(b*H+h)*C+c head slice of Q/K, out z*S*S).
// MODE 2: ctx (A = attn slab z, B = transposed-V head slice, out head slice).
// ---------------------------------------------------------------------------
constexpr int TBM = 128, TBK = 16;

template <int BN_, int MODE>
__global__ void __launch_bounds__((BN_ == 128) ? 512 : 256)
gemm_mma(const float* __restrict__ Ag, const float* __restrict__ Bg,
         float* __restrict__ Cg, int lda, int ldb, int ldc, int K,
         float alpha, const float* __restrict__ bias)
{
    constexpr int NTH     = (BN_ == 128) ? 512 : 256;
    constexpr int WARPS_N = BN_ / 32;                       // 4 or 2
    constexpr int NLD_A   = (TBM * TBK / 4) / NTH;          // 1 or 2
    constexpr int NLD_B   = (BN_ * TBK / 4) / NTH;          // 1

    __shared__ float As[TBK][TBM + 4];   // [k][m], pitch 132
    __shared__ float Bs[TBK][BN_ + 4];   // [k][n]

    const float* A  = Ag;
    const float* Bm = Bg;
    float* Cp = Cg;
    if (MODE == 1) {
        int z = blockIdx.z;
        int c = z % C_, h = (z / C_) % H_, b = z / (C_ * H_);
        size_t off = ((size_t)(b * C_ + c) * S_) * E_ + (size_t)h * HD_;
        A = Ag + off; Bm = Bg + off;
        Cp = Cg + (size_t)z * S_ * S_;
    }
    if (MODE == 2) {
        int z = blockIdx.z;
        int c = z % C_, h = (z / C_) % H_, b = z / (C_ * H_);
        A  = Ag + (size_t)z * S_ * S_;
        Bm = Bg + ((size_t)(b * C_ + c) * E_ + (size_t)h * HD_) * S_;
        Cp = Cg + (size_t)(b * C_ + c) * S_ * E_ + (size_t)h * HD_;
    }

    const int tid  = threadIdx.x;
    const int wid  = tid >> 5;
    const int lane = tid & 31;
    const int gid  = lane >> 2;     // group of 4
    const int tg   = lane & 3;      // thread in group

    const int warp_m = wid / WARPS_N;   // 0..3
    const int warp_n = wid % WARPS_N;   // 0..WARPS_N-1
    const int wm0 = warp_m * 32;
    const int wn0 = warp_n * 32;

    const int bm = blockIdx.y * TBM;
    const int bn = blockIdx.x * BN_;

    // Global tile-load plan: idx -> row = idx/4, k-chunk = idx%4 (float4)
    const float* pAg[NLD_A]; int arow[NLD_A], ak4[NLD_A];
#pragma unroll
    for (int j = 0; j < NLD_A; j++) {
        int idx = j * NTH + tid;
        arow[j] = idx >> 2; ak4[j] = idx & 3;
        pAg[j] = A + (size_t)(bm + arow[j]) * lda + ak4[j] * 4;
    }
    const float* pBg[NLD_B]; int brow[NLD_B], bk4[NLD_B];
#pragma unroll
    for (int j = 0; j < NLD_B; j++) {
        int idx = j * NTH + tid;
        brow[j] = idx >> 2; bk4[j] = idx & 3;
        pBg[j] = Bm + (size_t)(bn + brow[j]) * ldb + bk4[j] * 4;
    }

    float acc[2][4][4];
#pragma unroll
    for (int mt = 0; mt < 2; mt++)
#pragma unroll
        for (int nt = 0; nt < 4; nt++)
#pragma unroll
            for (int r = 0; r < 4; r++) acc[mt][nt][r] = 0.0f;

    float4 ra[NLD_A], rb[NLD_B];
#pragma unroll
    for (int j = 0; j < NLD_A; j++) ra[j] = *(const float4*)pAg[j];
#pragma unroll
    for (int j = 0; j < NLD_B; j++) rb[j] = *(const float4*)pBg[j];

    const int nslab = K / TBK;
    for (int kt = 0; kt < nslab; kt++) {
        // transposed stores with tf32 rounding
#pragma unroll
        for (int j = 0; j < NLD_A; j++) {
            float4 v = tf32x4(ra[j]);
            int kk = ak4[j] * 4, m = arow[j];
            As[kk + 0][m] = v.x; As[kk + 1][m] = v.y;
            As[kk + 2][m] = v.z; As[kk + 3][m] = v.w;
        }
#pragma unroll
        for (int j = 0; j < NLD_B; j++) {
            float4 v = tf32x4(rb[j]);
            int kk = bk4[j] * 4, n = brow[j];
            Bs[kk + 0][n] = v.x; Bs[kk + 1][n] = v.y;
            Bs[kk + 2][n] = v.z; Bs[kk + 3][n] = v.w;
        }
        __syncthreads();

        if (kt + 1 < nslab) {   // prefetch next slab into registers
#pragma unroll
            for (int j = 0; j < NLD_A; j++)
                ra[j] = *(const float4*)(pAg[j] + (size_t)(kt + 1) * TBK);
#pragma unroll
            for (int j = 0; j < NLD_B; j++)
                rb[j] = *(const float4*)(pBg[j] + (size_t)(kt + 1) * TBK);
        }

#pragma unroll
        for (int ks = 0; ks < TBK; ks += 8) {
            uint32_t af[2][4];
#pragma unroll
            for (int mt = 0; mt < 2; mt++) {
                int m0 = wm0 + mt * 16 + gid;
                af[mt][0] = __float_as_uint(As[ks + tg][m0]);
                af[mt][1] = __float_as_uint(As[ks + tg][m0 + 8]);
                af[mt][2] = __float_as_uint(As[ks + tg + 4][m0]);
                af[mt][3] = __float_as_uint(As[ks + tg + 4][m0 + 8]);
            }
            uint32_t bf[4][2];
#pragma unroll
            for (int nt = 0; nt < 4; nt++) {
                int n0 = wn0 + nt * 8 + gid;
                bf[nt][0] = __float_as_uint(Bs[ks + tg][n0]);
                bf[nt][1] = __float_as_uint(Bs[ks + tg + 4][n0]);
            }
#pragma unroll
            for (int mt = 0; mt < 2; mt++)
#pragma unroll
                for (int nt = 0; nt < 4; nt++)
                    mma_tf32(acc[mt][nt], af[mt], bf[nt]);
        }
        __syncthreads();
    }

    // Epilogue: c0/c1 -> (row, 2tg), (row, 2tg+1); c2/c3 -> row+8
#pragma unroll
    for (int mt = 0; mt < 2; mt++) {
#pragma unroll
        for (int nt = 0; nt < 4; nt++) {
            int row = bm + wm0 + mt * 16 + gid;
            int col = bn + wn0 + nt * 8 + tg * 2;
            float2 bb = make_float2(0.0f, 0.0f);
            if (bias) bb = *(const float2*)(bias + col);
            float2 v0, v1;
            v0.x = acc[mt][nt][0] * alpha + bb.x;
            v0.y = acc[mt][nt][1] * alpha + bb.y;
            v1.x = acc[mt][nt][2] * alpha + bb.x;
            v1.y = acc[mt][nt][3] * alpha + bb.y;
            *(float2*)(Cp + (size_t)row * ldc + col)       = v0;
            *(float2*)(Cp + (size_t)(row + 8) * ldc + col) = v1;
        }
    }
}

// ---------------------------------------------------------------------------
// Per-(b,c) 512x512 transpose of the V projection (token-major -> [e][s])
// so the ctx GEMM sees a K-major (TN) B operand.
// ---------------------------------------------------------------------------
__global__ void transpose512(const float* __restrict__ in, float* __restrict__ out)
{
    __shared__ float t[32][33];
    const size_t base = (size_t)blockIdx.z * 512 * 512;
    const float* I = in + base;
    float* O = out + base;
    int x = blockIdx.x * 32 + threadIdx.x;   // e
    int y = blockIdx.y * 32 + threadIdx.y;   // s
#pragma unroll
    for (int i = 0; i < 32; i += 8)
        t[threadIdx.y + i][threadIdx.x] = I[(size_t)(y + i) * 512 + x];
    __syncthreads();
    int x2 = blockIdx.y * 32 + threadIdx.x;  // s
    int y2 = blockIdx.x * 32 + threadIdx.y;  // e
#pragma unroll
    for (int i = 0; i < 32; i += 8)
        O[(size_t)(y2 + i) * 512 + x2] = t[threadIdx.x][threadIdx.y + i];
}

// ---------------------------------------------------------------------------
// Row softmax, in place, rows of exactly 512 floats. One warp per row.
// ---------------------------------------------------------------------------
__global__ void softmax_rows(float* __restrict__ attn)
{
    const int warp = (blockIdx.x * blockDim.x + threadIdx.x) >> 5;
    const int lane = threadIdx.x & 31;
    float* row = attn + (size_t)warp * S_;

    float4 v[4];
    float mx = -3.0e38f;
#pragma unroll
    for (int i = 0; i < 4; i++) {
        v[i] = *(const float4*)(row + (size_t)(lane + 32 * i) * 4);
        mx = fmaxf(mx, fmaxf(fmaxf(v[i].x, v[i].y), fmaxf(v[i].z, v[i].w)));
    }
#pragma unroll
    for (int s = 16; s > 0; s >>= 1)
        mx = fmaxf(mx, __shfl_xor_sync(0xffffffffu, mx, s));

    float sum = 0.0f;
#pragma unroll
    for (int i = 0; i < 4; i++) {
        v[i].x = __expf(v[i].x - mx); v[i].y = __expf(v[i].y - mx);
        v[i].z = __expf(v[i].z - mx); v[i].w = __expf(v[i].w - mx);
        sum += v[i].x + v[i].y + v[i].z + v[i].w;
    }
#pragma unroll
    for (int s = 16; s > 0; s >>= 1)
        sum += __shfl_xor_sync(0xffffffffu, sum, s);

    const float inv = 1.0f / sum;
#pragma unroll
    for (int i = 0; i < 4; i++) {
        v[i].x *= inv; v[i].y *= inv; v[i].z *= inv; v[i].w *= inv;
        *(float4*)(row + (size_t)(lane + 32 * i) * 4) = v[i];
    }
}

// ---------------------------------------------------------------------------
// Launch (graph-capturable: kernel launches only)
// ---------------------------------------------------------------------------
extern "C" void kernel_launch(void* const* d_in, const int* in_sizes, int n_in,
                              void* d_out, int out_size)
{
    const float* q  = (const float*)d_in[0];
    const float* k  = (const float*)d_in[1];
    const float* v  = (const float*)d_in[2];
    const float* Wq = (const float*)d_in[3];
    const float* bq = (const float*)d_in[4];
    const float* Wk = (const float*)d_in[5];
    const float* bk = (const float*)d_in[6];
    const float* Wv = (const float*)d_in[7];
    const float* bv = (const float*)d_in[8];
    const float* Wo = (const float*)d_in[9];
    const float* bo = (const float*)d_in[10];
    float* out = (float*)d_out;

    float *gq, *gk, *gv, *gvt, *gctx, *gfb;
    cudaGetSymbolAddress((void**)&gq,   g_q);
    cudaGetSymbolAddress((void**)&gk,   g_k);
    cudaGetSymbolAddress((void**)&gv,   g_v);
    cudaGetSymbolAddress((void**)&gvt,  g_vt);
    cudaGetSymbolAddress((void**)&gctx, g_ctx);
    cudaGetSymbolAddress((void**)&gfb,  g_attn_fb);

    float* attn = ((size_t)out_size >= OUT_ELEMS + ATTN_ELEMS)
                      ? (out + OUT_ELEMS) : gfb;

    // 1-3) Q/K/V projections: (32768 x 512) = X @ W^T + b
    dim3 gproj(E_ / 128, TOKENS_ / TBM, 1);
    gemm_mma<128, 0><<<gproj, 512>>>(q, Wq, gq, E_, E_, E_, E_, 1.0f, bq);
    gemm_mma<128, 0><<<gproj, 512>>>(k, Wk, gk, E_, E_, E_, E_, 1.0f, bk);
    gemm_mma<128, 0><<<gproj, 512>>>(v, Wv, gv, E_, E_, E_, E_, 1.0f, bv);

    // 3b) transpose V projection per (b,c) so ctx's B operand is K-major
    transpose512<<<dim3(16, 16, B_ * C_), dim3(32, 8)>>>(gv, gvt);

    // 4) scores = (Q @ K^T) / 8 per (b,h,c)
    dim3 gsc(S_ / 128, S_ / TBM, B_ * H_ * C_);
    gemm_mma<128, 1><<<gsc, 512>>>(gq, gk, attn, E_, E_, S_, HD_, 0.125f, nullptr);

    // 5) softmax over rows of 512, in place
    softmax_rows<<<(B_ * H_ * C_ * S_) / 8, 256>>>(attn);

    // 6) context = attn @ V (heads merged into (b,c,s,E))
    dim3 gcx(1, S_ / TBM, B_ * H_ * C_);
    gemm_mma<64, 2><<<gcx, 256>>>(attn, gvt, gctx, S_, S_, E_, S_, 1.0f, nullptr);

    // 7) output projection
    gemm_mma<128, 0><<<gproj, 512>>>(gctx, Wo, out, E_, E_, E_, E_, 1.0f, bo);
}

// round 15
// speedup vs baseline: 1.4021x; 1.0001x over previous
#include <cuda_runtime.h>
#include <cstddef>
#include <cstdint>

// Problem constants
constexpr int B_ = 4, C_ = 16, S_ = 512, E_ = 512, H_ = 8, HD_ = 64;
constexpr int TOKENS_ = B_ * C_ * S_;                         // 32768
constexpr size_t OUT_ELEMS  = (size_t)TOKENS_ * E_;           // 16,777,216
constexpr size_t ATTN_ELEMS = (size_t)B_ * H_ * C_ * S_ * S_; // 134,217,728

// ---------------------------------------------------------------------------
// Scratch (__device__ globals: allocation APIs are banned)
// ---------------------------------------------------------------------------
__device__ __align__(128) float g_q[OUT_ELEMS];
__device__ __align__(128) float g_k[OUT_ELEMS];
__device__ __align__(128) float g_v[OUT_ELEMS];
__device__ __align__(128) float g_vt[OUT_ELEMS];   // per-(b,c) transposed V proj
__device__ __align__(128) float g_ctx[OUT_ELEMS];
__device__ __align__(128) float g_attn_fb[ATTN_ELEMS];

// ---------------------------------------------------------------------------
// tf32 helpers (baseline PTX, valid for sm_103 family target)
// ---------------------------------------------------------------------------
__device__ __forceinline__ float to_tf32(float x) {
    float r;
    asm("cvt.rna.tf32.f32 %0, %1;" : "=f"(r) : "f"(x));
    return r;
}
__device__ __forceinline__ float4 tf32x4(float4 v) {
    v.x = to_tf32(v.x); v.y = to_tf32(v.y);
    v.z = to_tf32(v.z); v.w = to_tf32(v.w);
    return v;
}
__device__ __forceinline__ void mma_tf32(float* c, const uint32_t* a, const uint32_t* b) {
    asm volatile(
        "mma.sync.aligned.m16n8k8.row.col.f32.tf32.tf32.f32 "
        "{%0,%1,%2,%3}, {%4,%5,%6,%7}, {%8,%9}, {%0,%1,%2,%3};"
        : "+f"(c[0]), "+f"(c[1]), "+f"(c[2]), "+f"(c[3])
        : "r"(a[0]), "r"(a[1]), "r"(a[2]), "r"(a[3]), "r"(b[0]), "r"(b[1]));
}

// ---------------------------------------------------------------------------
// tf32 mma.sync GEMM (TN): C[M,N] = alpha * A[M,K] @ B[N,K]^T (+ bias[N])
// BM=128, BK=16. BN_=128 -> 512 threads (4x4 warps); BN_=64 -> 256 (4x2).
// Warp tile 32x32 = 2x4 m16n8k8 tiles. Register-prefetch double buffering.
// MODE 0: plain. MODE 1: scores (z=(b*H+h)*C+c head slice of Q/K, out z*S*S).
// MODE 2: ctx (A = attn slab z, B = transposed-V head slice, out head slice).
// ---------------------------------------------------------------------------
constexpr int TBM = 128, TBK = 16;

template <int BN_, int MODE>
__global__ void __launch_bounds__((BN_ == 128) ? 512 : 256)
gemm_mma(const float* __restrict__ Ag, const float* __restrict__ Bg,
         float* __restrict__ Cg, int lda, int ldb, int ldc, int K,
         float alpha, const float* __restrict__ bias)
{
    constexpr int NTH     = (BN_ == 128) ? 512 : 256;
    constexpr int WARPS_N = BN_ / 32;                       // 4 or 2
    constexpr int NLD_A   = (TBM * TBK / 4) / NTH;          // 1 or 2
    constexpr int NLD_B   = (BN_ * TBK / 4) / NTH;          // 1

    __shared__ float As[TBK][TBM + 4];   // [k][m], pitch 132
    __shared__ float Bs[TBK][BN_ + 4];   // [k][n]

    const float* A  = Ag;
    const float* Bm = Bg;
    float* Cp = Cg;
    if (MODE == 1) {
        int z = blockIdx.z;
        int c = z % C_, h = (z / C_) % H_, b = z / (C_ * H_);
        size_t off = ((size_t)(b * C_ + c) * S_) * E_ + (size_t)h * HD_;
        A = Ag + off; Bm = Bg + off;
        Cp = Cg + (size_t)z * S_ * S_;
    }
    if (MODE == 2) {
        int z = blockIdx.z;
        int c = z % C_, h = (z / C_) % H_, b = z / (C_ * H_);
        A  = Ag + (size_t)z * S_ * S_;
        Bm = Bg + ((size_t)(b * C_ + c) * E_ + (size_t)h * HD_) * S_;
        Cp = Cg + (size_t)(b * C_ + c) * S_ * E_ + (size_t)h * HD_;
    }

    const int tid  = threadIdx.x;
    const int wid  = tid >> 5;
    const int lane = tid & 31;
    const int gid  = lane >> 2;     // group of 4
    const int tg   = lane & 3;      // thread in group

    const int warp_m = wid / WARPS_N;   // 0..3
    const int warp_n = wid % WARPS_N;   // 0..WARPS_N-1
    const int wm0 = warp_m * 32;
    const int wn0 = warp_n * 32;

    const int bm = blockIdx.y * TBM;
    const int bn = blockIdx.x * BN_;

    // Global tile-load plan: idx -> row = idx/4, k-chunk = idx%4 (float4)
    const float* pAg[NLD_A]; int arow[NLD_A], ak4[NLD_A];
#pragma unroll
    for (int j = 0; j < NLD_A; j++) {
        int idx = j * NTH + tid;
        arow[j] = idx >> 2; ak4[j] = idx & 3;
        pAg[j] = A + (size_t)(bm + arow[j]) * lda + ak4[j] * 4;
    }
    const float* pBg[NLD_B]; int brow[NLD_B], bk4[NLD_B];
#pragma unroll
    for (int j = 0; j < NLD_B; j++) {
        int idx = j * NTH + tid;
        brow[j] = idx >> 2; bk4[j] = idx & 3;
        pBg[j] = Bm + (size_t)(bn + brow[j]) * ldb + bk4[j] * 4;
    }

    float acc[2][4][4];
#pragma unroll
    for (int mt = 0; mt < 2; mt++)
#pragma unroll
        for (int nt = 0; nt < 4; nt++)
#pragma unroll
            for (int r = 0; r < 4; r++) acc[mt][nt][r] = 0.0f;

    float4 ra[NLD_A], rb[NLD_B];
#pragma unroll
    for (int j = 0; j < NLD_A; j++) ra[j] = *(const float4*)pAg[j];
#pragma unroll
    for (int j = 0; j < NLD_B; j++) rb[j] = *(const float4*)pBg[j];

    const int nslab = K / TBK;
    for (int kt = 0; kt < nslab; kt++) {
        // transposed stores with tf32 rounding
#pragma unroll
        for (int j = 0; j < NLD_A; j++) {
            float4 v = tf32x4(ra[j]);
            int kk = ak4[j] * 4, m = arow[j];
            As[kk + 0][m] = v.x; As[kk + 1][m] = v.y;
            As[kk + 2][m] = v.z; As[kk + 3][m] = v.w;
        }
#pragma unroll
        for (int j = 0; j < NLD_B; j++) {
            float4 v = tf32x4(rb[j]);
            int kk = bk4[j] * 4, n = brow[j];
            Bs[kk + 0][n] = v.x; Bs[kk + 1][n] = v.y;
            Bs[kk + 2][n] = v.z; Bs[kk + 3][n] = v.w;
        }
        __syncthreads();

        if (kt + 1 < nslab) {   // prefetch next slab into registers
#pragma unroll
            for (int j = 0; j < NLD_A; j++)
                ra[j] = *(const float4*)(pAg[j] + (size_t)(kt + 1) * TBK);
#pragma unroll
            for (int j = 0; j < NLD_B; j++)
                rb[j] = *(const float4*)(pBg[j] + (size_t)(kt + 1) * TBK);
        }

#pragma unroll
        for (int ks = 0; ks < TBK; ks += 8) {
            uint32_t af[2][4];
#pragma unroll
            for (int mt = 0; mt < 2; mt++) {
                int m0 = wm0 + mt * 16 + gid;
                af[mt][0] = __float_as_uint(As[ks + tg][m0]);
                af[mt][1] = __float_as_uint(As[ks + tg][m0 + 8]);
                af[mt][2] = __float_as_uint(As[ks + tg + 4][m0]);
                af[mt][3] = __float_as_uint(As[ks + tg + 4][m0 + 8]);
            }
            uint32_t bf[4][2];
#pragma unroll
            for (int nt = 0; nt < 4; nt++) {
                int n0 = wn0 + nt * 8 + gid;
                bf[nt][0] = __float_as_uint(Bs[ks + tg][n0]);
                bf[nt][1] = __float_as_uint(Bs[ks + tg + 4][n0]);
            }
#pragma unroll
            for (int mt = 0; mt < 2; mt++)
#pragma unroll
                for (int nt = 0; nt < 4; nt++)
                    mma_tf32(acc[mt][nt], af[mt], bf[nt]);
        }
        __syncthreads();
    }

    // Epilogue: c0/c1 -> (row, 2tg), (row, 2tg+1); c2/c3 -> row+8
#pragma unroll
    for (int mt = 0; mt < 2; mt++) {
#pragma unroll
        for (int nt = 0; nt < 4; nt++) {
            int row = bm + wm0 + mt * 16 + gid;
            int col = bn + wn0 + nt * 8 + tg * 2;
            float2 bb = make_float2(0.0f, 0.0f);
            if (bias) bb = *(const float2*)(bias + col);
            float2 v0, v1;
            v0.x = acc[mt][nt][0] * alpha + bb.x;
            v0.y = acc[mt][nt][1] * alpha + bb.y;
            v1.x = acc[mt][nt][2] * alpha + bb.x;
            v1.y = acc[mt][nt][3] * alpha + bb.y;
            *(float2*)(Cp + (size_t)row * ldc + col)       = v0;
            *(float2*)(Cp + (size_t)(row + 8) * ldc + col) = v1;
        }
    }
}

// ---------------------------------------------------------------------------
// Per-(b,c) 512x512 transpose of the V projection (token-major -> [e][s])
// so the ctx GEMM sees a K-major (TN) B operand.
// ---------------------------------------------------------------------------
__global__ void transpose512(const float* __restrict__ in, float* __restrict__ out)
{
    __shared__ float t[32][33];
    const size_t base = (size_t)blockIdx.z * 512 * 512;
    const float* I = in + base;
    float* O = out + base;
    int x = blockIdx.x * 32 + threadIdx.x;   // e
    int y = blockIdx.y * 32 + threadIdx.y;   // s
#pragma unroll
    for (int i = 0; i < 32; i += 8)
        t[threadIdx.y + i][threadIdx.x] = I[(size_t)(y + i) * 512 + x];
    __syncthreads();
    int x2 = blockIdx.y * 32 + threadIdx.x;  // s
    int y2 = blockIdx.x * 32 + threadIdx.y;  // e
#pragma unroll
    for (int i = 0; i < 32; i += 8)
        O[(size_t)(y2 + i) * 512 + x2] = t[threadIdx.x][threadIdx.y + i];
}

// ---------------------------------------------------------------------------
// Row softmax, in place, rows of exactly 512 floats. One warp per row.
// ---------------------------------------------------------------------------
__global__ void softmax_rows(float* __restrict__ attn)
{
    const int warp = (blockIdx.x * blockDim.x + threadIdx.x) >> 5;
    const int lane = threadIdx.x & 31;
    float* row = attn + (size_t)warp * S_;

    float4 v[4];
    float mx = -3.0e38f;
#pragma unroll
    for (int i = 0; i < 4; i++) {
        v[i] = *(const float4*)(row + (size_t)(lane + 32 * i) * 4);
        mx = fmaxf(mx, fmaxf(fmaxf(v[i].x, v[i].y), fmaxf(v[i].z, v[i].w)));
    }
#pragma unroll
    for (int s = 16; s > 0; s >>= 1)
        mx = fmaxf(mx, __shfl_xor_sync(0xffffffffu, mx, s));

    float sum = 0.0f;
#pragma unroll
    for (int i = 0; i < 4; i++) {
        v[i].x = __expf(v[i].x - mx); v[i].y = __expf(v[i].y - mx);
        v[i].z = __expf(v[i].z - mx); v[i].w = __expf(v[i].w - mx);
        sum += v[i].x + v[i].y + v[i].z + v[i].w;
    }
#pragma unroll
    for (int s = 16; s > 0; s >>= 1)
        sum += __shfl_xor_sync(0xffffffffu, sum, s);

    const float inv = 1.0f / sum;
#pragma unroll
    for (int i = 0; i < 4; i++) {
        v[i].x *= inv; v[i].y *= inv; v[i].z *= inv; v[i].w *= inv;
        *(float4*)(row + (size_t)(lane + 32 * i) * 4) = v[i];
    }
}

// ---------------------------------------------------------------------------
// Launch (graph-capturable: kernel launches only)
// ---------------------------------------------------------------------------
extern "C" void kernel_launch(void* const* d_in, const int* in_sizes, int n_in,
                              void* d_out, int out_size)
{
    const float* q  = (const float*)d_in[0];
    const float* k  = (const float*)d_in[1];
    const float* v  = (const float*)d_in[2];
    const float* Wq = (const float*)d_in[3];
    const float* bq = (const float*)d_in[4];
    const float* Wk = (const float*)d_in[5];
    const float* bk = (const float*)d_in[6];
    const float* Wv = (const float*)d_in[7];
    const float* bv = (const float*)d_in[8];
    const float* Wo = (const float*)d_in[9];
    const float* bo = (const float*)d_in[10];
    float* out = (float*)d_out;

    float *gq, *gk, *gv, *gvt, *gctx, *gfb;
    cudaGetSymbolAddress((void**)&gq,   g_q);
    cudaGetSymbolAddress((void**)&gk,   g_k);
    cudaGetSymbolAddress((void**)&gv,   g_v);
    cudaGetSymbolAddress((void**)&gvt,  g_vt);
    cudaGetSymbolAddress((void**)&gctx, g_ctx);
    cudaGetSymbolAddress((void**)&gfb,  g_attn_fb);

    float* attn = ((size_t)out_size >= OUT_ELEMS + ATTN_ELEMS)
                      ? (out + OUT_ELEMS) : gfb;

    // 1-3) Q/K/V projections: (32768 x 512) = X @ W^T + b
    dim3 gproj(E_ / 128, TOKENS_ / TBM, 1);
    gemm_mma<128, 0><<<gproj, 512>>>(q, Wq, gq, E_, E_, E_, E_, 1.0f, bq);
    gemm_mma<128, 0><<<gproj, 512>>>(k, Wk, gk, E_, E_, E_, E_, 1.0f, bk);
    gemm_mma<128, 0><<<gproj, 512>>>(v, Wv, gv, E_, E_, E_, E_, 1.0f, bv);

    // 3b) transpose V projection per (b,c) so ctx's B operand is K-major
    transpose512<<<dim3(16, 16, B_ * C_), dim3(32, 8)>>>(gv, gvt);

    // 4) scores = (Q @ K^T) / 8 per (b,h,c)
    dim3 gsc(S_ / 128, S_ / TBM, B_ * H_ * C_);
    gemm_mma<128, 1><<<gsc, 512>>>(gq, gk, attn, E_, E_, S_, HD_, 0.125f, nullptr);

    // 5) softmax over rows of 512, in place
    softmax_rows<<<(B_ * H_ * C_ * S_) / 8, 256>>>(attn);

    // 6) context = attn @ V (heads merged into (b,c,s,E))
    dim3 gcx(1, S_ / TBM, B_ * H_ * C_);
    gemm_mma<64, 2><<<gcx, 256>>>(attn, gvt, gctx, S_, S_, E_, S_, 1.0f, nullptr);

    // 7) output projection
    gemm_mma<128, 0><<<gproj, 512>>>(gctx, Wo, out, E_, E_, E_, E_, 1.0f, bo);
}